// round 1
// baseline (speedup 1.0000x reference)
#include <cuda_runtime.h>

// Problem constants (match reference)
#define B_ 8
#define S_ 2048
#define N_ 512
#define D_ 1024
#define MAX_W_ 32
#define MASK_FILL_ (-1000.0f)

// Scratch for global attention logits (B*S floats = 64 KB) — __device__ global
// per allocation rules.
__device__ float g_logits[B_ * S_];

// Kernel 1: logits[b,s] = dot(seq[b,s,:], att_w) + att_b
// One warp per row. Each lane loads 8 float4 (32 floats), warp-reduce.
__global__ void __launch_bounds__(256)
logits_kernel(const float* __restrict__ seq,
              const float* __restrict__ att_w,
              const float* __restrict__ att_b) {
    int warp = (blockIdx.x * blockDim.x + threadIdx.x) >> 5;
    int lane = threadIdx.x & 31;
    if (warp >= B_ * S_) return;

    const float4* row = reinterpret_cast<const float4*>(seq + (size_t)warp * D_);
    const float4* w4  = reinterpret_cast<const float4*>(att_w);

    float acc = 0.0f;
    #pragma unroll
    for (int i = 0; i < (D_ / 4) / 32; i++) {   // 8 iterations
        float4 a = row[lane + i * 32];
        float4 w = w4[lane + i * 32];
        acc += a.x * w.x + a.y * w.y + a.z * w.z + a.w * w.w;
    }
    #pragma unroll
    for (int off = 16; off; off >>= 1)
        acc += __shfl_xor_sync(0xffffffffu, acc, off);

    if (lane == 0)
        g_logits[warp] = acc + att_b[0];
}

// Kernel 2: one CTA per (b,n) span.
//   warp 0: build masked logits (exactly like reference: MASK_FILL where
//           masked, then standard softmax over all 32), stash attn + idx in smem.
//   all 256 threads: each owns one float4 column of D, accumulates the
//           weighted sum over 32 (contiguous, coalesced) sequence rows.
__global__ void __launch_bounds__(256)
span_kernel(const float* __restrict__ seq,
            const int*   __restrict__ spans,
            float*       __restrict__ out) {
    __shared__ float s_attn[MAX_W_];
    __shared__ int   s_idx[MAX_W_];

    const int bn = blockIdx.x;        // 0 .. B*N-1
    const int b  = bn / N_;
    const int tid = threadIdx.x;

    if (tid < 32) {
        const int start = spans[bn * 2 + 0];
        const int end   = spans[bn * 2 + 1];     // inclusive
        const int width = end - start;
        const int raw   = end - tid;
        const bool m    = (tid <= width) && (raw >= 0);
        const int  idx  = raw > 0 ? raw : 0;

        float logit = m ? g_logits[b * S_ + idx] : MASK_FILL_;

        float mx = logit;
        #pragma unroll
        for (int off = 16; off; off >>= 1)
            mx = fmaxf(mx, __shfl_xor_sync(0xffffffffu, mx, off));
        float e = __expf(logit - mx);
        float sum = e;
        #pragma unroll
        for (int off = 16; off; off >>= 1)
            sum += __shfl_xor_sync(0xffffffffu, sum, off);

        s_attn[tid] = e / sum;
        s_idx[tid]  = idx;
    }
    __syncthreads();

    const float4* seqb = reinterpret_cast<const float4*>(seq + (size_t)b * S_ * D_);

    float4 acc = make_float4(0.f, 0.f, 0.f, 0.f);
    #pragma unroll 8
    for (int w = 0; w < MAX_W_; w++) {
        const float a = s_attn[w];
        const float4 v = seqb[(size_t)s_idx[w] * (D_ / 4) + tid];
        acc.x += a * v.x;
        acc.y += a * v.y;
        acc.z += a * v.z;
        acc.w += a * v.w;
    }

    reinterpret_cast<float4*>(out)[(size_t)bn * (D_ / 4) + tid] = acc;
}

extern "C" void kernel_launch(void* const* d_in, const int* in_sizes, int n_in,
                              void* d_out, int out_size) {
    const float* seq   = (const float*)d_in[0];   // (B, S, D) f32
    const int*   spans = (const int*)  d_in[1];   // (B, N, 2) i32
    const float* att_w = (const float*)d_in[2];   // (D, 1) f32
    const float* att_b = (const float*)d_in[3];   // (1,) f32
    float* out = (float*)d_out;                   // (B, N, D) f32

    // Kernel 1: B*S = 16384 rows, 8 warps/block -> 2048 blocks
    logits_kernel<<<(B_ * S_) / 8, 256>>>(seq, att_w, att_b);

    // Kernel 2: B*N = 4096 CTAs, 256 threads (one float4 column each)
    span_kernel<<<B_ * N_, 256>>>(seq, spans, out);
}

// round 2
// speedup vs baseline: 1.3279x; 1.3279x over previous
#include <cuda_runtime.h>

// Problem constants (match reference)
#define B_ 8
#define S_ 2048
#define N_ 512
#define D_ 1024
#define MAX_W_ 32
#define MASK_FILL_ (-1000.0f)

// Scratch for global attention logits (B*S floats = 64 KB).
__device__ float g_logits[B_ * S_];

// Kernel 1: logits[b,s] = dot(seq[b,s,:], att_w) + att_b
__global__ void __launch_bounds__(256)
logits_kernel(const float* __restrict__ seq,
              const float* __restrict__ att_w,
              const float* __restrict__ att_b) {
    int warp = (blockIdx.x * blockDim.x + threadIdx.x) >> 5;
    int lane = threadIdx.x & 31;
    if (warp >= B_ * S_) return;

    const float4* row = reinterpret_cast<const float4*>(seq + (size_t)warp * D_);
    const float4* w4  = reinterpret_cast<const float4*>(att_w);

    float acc = 0.0f;
    #pragma unroll
    for (int i = 0; i < (D_ / 4) / 32; i++) {   // 8 iterations
        float4 a = row[lane + i * 32];
        float4 w = w4[lane + i * 32];
        acc += a.x * w.x + a.y * w.y + a.z * w.z + a.w * w.w;
    }
    #pragma unroll
    for (int off = 16; off; off >>= 1)
        acc += __shfl_xor_sync(0xffffffffu, acc, off);

    if (lane == 0)
        g_logits[warp] = acc + att_b[0];
}

// Kernel 2: one CTA per (b,n) span. Only the width+1 VALID rows [start..end]
// are loaded — masked positions have softmax weight exactly 0.0f (exp(-1000-mx)
// underflows), identical to the reference's arithmetic.
//
// s_attn is stored row-ascending: s_attn[j] = weight of row (start + j).
__global__ void __launch_bounds__(256)
span_kernel(const float* __restrict__ seq,
            const int*   __restrict__ spans,
            float*       __restrict__ out) {
    __shared__ float s_attn[MAX_W_];
    __shared__ int   s_start;
    __shared__ int   s_nvalid;

    const int bn  = blockIdx.x;       // 0 .. B*N-1
    const int b   = bn / N_;
    const int tid = threadIdx.x;

    if (tid < 32) {
        const int start = spans[bn * 2 + 0];
        const int end   = spans[bn * 2 + 1];      // inclusive
        const int width = end - start;            // 0..31
        const bool m    = (tid <= width);          // raw>=0 implied by start>=0
        const int  idx  = m ? (end - tid) : 0;

        float logit = m ? g_logits[b * S_ + idx] : MASK_FILL_;

        float mx = logit;
        #pragma unroll
        for (int off = 16; off; off >>= 1)
            mx = fmaxf(mx, __shfl_xor_sync(0xffffffffu, mx, off));
        float e = m ? __expf(logit - mx) : 0.0f;
        float sum = e;
        #pragma unroll
        for (int off = 16; off; off >>= 1)
            sum += __shfl_xor_sync(0xffffffffu, sum, off);

        // row-ascending storage: row start+j has w = width - j
        if (m) s_attn[width - tid] = e / sum;
        if (tid == 0) { s_start = start; s_nvalid = width + 1; }
    }
    __syncthreads();

    const int start = s_start;
    const int nv    = s_nvalid;

    // Each thread owns one float4 column of D.
    const float4* base = reinterpret_cast<const float4*>(seq)
                       + ((size_t)b * S_ + start) * (D_ / 4) + tid;

    float4 acc = make_float4(0.f, 0.f, 0.f, 0.f);

    int j = 0;
    // Unroll by 4 with batched loads for MLP against L2 latency.
    for (; j + 4 <= nv; j += 4) {
        float4 v0 = base[(size_t)(j + 0) * (D_ / 4)];
        float4 v1 = base[(size_t)(j + 1) * (D_ / 4)];
        float4 v2 = base[(size_t)(j + 2) * (D_ / 4)];
        float4 v3 = base[(size_t)(j + 3) * (D_ / 4)];
        float a0 = s_attn[j + 0], a1 = s_attn[j + 1];
        float a2 = s_attn[j + 2], a3 = s_attn[j + 3];
        acc.x += a0 * v0.x; acc.y += a0 * v0.y; acc.z += a0 * v0.z; acc.w += a0 * v0.w;
        acc.x += a1 * v1.x; acc.y += a1 * v1.y; acc.z += a1 * v1.z; acc.w += a1 * v1.w;
        acc.x += a2 * v2.x; acc.y += a2 * v2.y; acc.z += a2 * v2.z; acc.w += a2 * v2.w;
        acc.x += a3 * v3.x; acc.y += a3 * v3.y; acc.z += a3 * v3.z; acc.w += a3 * v3.w;
    }
    for (; j < nv; j++) {
        float4 v = base[(size_t)j * (D_ / 4)];
        float a = s_attn[j];
        acc.x += a * v.x; acc.y += a * v.y; acc.z += a * v.z; acc.w += a * v.w;
    }

    reinterpret_cast<float4*>(out)[(size_t)bn * (D_ / 4) + tid] = acc;
}

extern "C" void kernel_launch(void* const* d_in, const int* in_sizes, int n_in,
                              void* d_out, int out_size) {
    const float* seq   = (const float*)d_in[0];   // (B, S, D) f32
    const int*   spans = (const int*)  d_in[1];   // (B, N, 2) i32
    const float* att_w = (const float*)d_in[2];   // (D, 1) f32
    const float* att_b = (const float*)d_in[3];   // (1,) f32
    float* out = (float*)d_out;                   // (B, N, D) f32

    logits_kernel<<<(B_ * S_) / 8, 256>>>(seq, att_w, att_b);
    span_kernel<<<B_ * N_, 256>>>(seq, spans, out);
}